// round 16
// baseline (speedup 1.0000x reference)
#include <cuda_runtime.h>
#include <math.h>

// x[1, 2M, 16] fp32, ~5% NaN. Per-column mean of valid entries; NaNs -> mean.
//
// Two plain kernels in the graph (kernel boundary = global sync; hardware
// CTA wave scheduling load-balances block finish-time spread for free):
//   reduce: 4096 small blocks (2048 float4 = 32KB each) -> per-column
//           sum/count -> global atomics
//   fill:   same block layout; reload (__ldcs, mostly L2-hot), NaN->mean,
//           store (__stcs). Last fill block resets global accumulators.

#define C 16
#define THREADS 256
#define CHUNK4 2048LL   // float4s per block (8 iters/thread)

struct Acc {
    float sum[C];
    float cnt[C];
    unsigned int done;
};
__device__ Acc g_acc;   // static-zeroed; self-reset by fill's last block

__global__ void __launch_bounds__(THREADS)
reduce_kernel(const float4* __restrict__ in, long long n4) {
    __shared__ float s_sum[C];
    __shared__ float s_cnt[C];

    const int t = threadIdx.x;
    if (t < C) { s_sum[t] = 0.0f; s_cnt[t] = 0.0f; }
    __syncthreads();

    const long long base  = (long long)blockIdx.x * CHUNK4;
    const long long end   = (base + CHUNK4 < n4) ? (base + CHUNK4) : n4;
    const long long start = base + t;
    const int cbase = ((int)(start & 3)) * 4;   // loop-invariant column group

    float ls0 = 0.f, ls1 = 0.f, ls2 = 0.f, ls3 = 0.f;
    float lc0 = 0.f, lc1 = 0.f, lc2 = 0.f, lc3 = 0.f;

    #pragma unroll 8
    for (long long i = start; i < end; i += THREADS) {
        float4 v = in[i];
        if (v.x == v.x) { ls0 += v.x; lc0 += 1.f; }
        if (v.y == v.y) { ls1 += v.y; lc1 += 1.f; }
        if (v.z == v.z) { ls2 += v.z; lc2 += 1.f; }
        if (v.w == v.w) { ls3 += v.w; lc3 += 1.f; }
    }

    atomicAdd(&s_sum[cbase + 0], ls0);
    atomicAdd(&s_sum[cbase + 1], ls1);
    atomicAdd(&s_sum[cbase + 2], ls2);
    atomicAdd(&s_sum[cbase + 3], ls3);
    atomicAdd(&s_cnt[cbase + 0], lc0);
    atomicAdd(&s_cnt[cbase + 1], lc1);
    atomicAdd(&s_cnt[cbase + 2], lc2);
    atomicAdd(&s_cnt[cbase + 3], lc3);
    __syncthreads();

    if (t < C) {
        atomicAdd(&g_acc.sum[t], s_sum[t]);
        atomicAdd(&g_acc.cnt[t], s_cnt[t]);
    }
}

__global__ void __launch_bounds__(THREADS)
fill_kernel(const float4* __restrict__ in, float4* __restrict__ out,
            long long n4) {
    __shared__ float s_mean[C];

    const int t = threadIdx.x;
    if (t < C) {
        s_mean[t] = g_acc.sum[t] / fmaxf(g_acc.cnt[t], 1.0f);
    }
    __syncthreads();

    const long long base  = (long long)blockIdx.x * CHUNK4;
    const long long end   = (base + CHUNK4 < n4) ? (base + CHUNK4) : n4;
    const long long start = base + t;
    const int cbase = ((int)(start & 3)) * 4;

    const float m0 = s_mean[cbase + 0];
    const float m1 = s_mean[cbase + 1];
    const float m2 = s_mean[cbase + 2];
    const float m3 = s_mean[cbase + 3];

    #pragma unroll 8
    for (long long i = start; i < end; i += THREADS) {
        float4 v = __ldcs(&in[i]);
        if (!(v.x == v.x)) v.x = m0;
        if (!(v.y == v.y)) v.y = m1;
        if (!(v.z == v.z)) v.z = m2;
        if (!(v.w == v.w)) v.w = m3;
        __stcs(&out[i], v);
    }

    // ---------- self-reset by last finished block ----------
    __syncthreads();
    if (t == 0) {
        __threadfence();
        unsigned int ticket = atomicAdd(&g_acc.done, 1u);
        if (ticket == gridDim.x - 1) {
            #pragma unroll
            for (int c = 0; c < C; c++) { g_acc.sum[c] = 0.0f; g_acc.cnt[c] = 0.0f; }
            g_acc.done = 0u;
            __threadfence();
        }
    }
}

extern "C" void kernel_launch(void* const* d_in, const int* in_sizes, int n_in,
                              void* d_out, int out_size) {
    const float4* in = (const float4*)d_in[0];
    float4* out      = (float4*)d_out;
    long long n  = (long long)in_sizes[0];
    long long n4 = n / 4;

    int grid = (int)((n4 + CHUNK4 - 1) / CHUNK4);   // ~4096 blocks

    reduce_kernel<<<grid, THREADS>>>(in, n4);
    fill_kernel<<<grid, THREADS>>>(in, out, n4);
}